// round 8
// baseline (speedup 1.0000x reference)
#include <cuda_runtime.h>
#include <math.h>
#include <stdint.h>

// Problem: B=4, S=4096, D=2048, E=64, K=2
#define M_TOKENS 16384
#define D_DIM    2048
#define E_EXP    64
#define TM       128
#define NCTA     (M_TOKENS / TM)       // 128
#define NTHREADS 256
#define NCH      64                    // k32 chunks

// Token split: tensor path tokens [0,48), fma2 path tokens [48,128)
#define MT       48

// Stage layout (bytes): xs [128 tok x 36f], ws [64 exp x 36f], wt [32k x 16 gran x 16B]
#define XS_OFF   0
#define XS_BYTES (128 * 36 * 4)        // 18432
#define WS_OFF   XS_BYTES
#define WS_BYTES (64 * 36 * 4)         // 9216
#define WT_OFF   (WS_OFF + WS_BYTES)   // 27648
#define WT_BYTES (32 * 16 * 16)        // 8192
#define STAGE_BYTES (WT_OFF + WT_BYTES)    // 35840
#define DYN_BYTES   (2 * STAGE_BYTES)      // 71680

__device__ float g_partials[NCTA * 128];
// Full-K W transpose image: granule (k,q) = experts 4q..4q+3 at column k
__device__ __align__(16) float g_wt[D_DIM * E_EXP];

#define CP16(smem_a, gptr) \
    asm volatile("cp.async.cg.shared.global [%0], [%1], 16;" \
                 :: "r"(smem_a), "l"(gptr) : "memory")
#define CP_COMMIT() asm volatile("cp.async.commit_group;" ::: "memory")
#define CP_WAIT1()  asm volatile("cp.async.wait_group 1;" ::: "memory")

static __device__ __forceinline__ uint32_t smem_u32(const void* p) {
    uint32_t r;
    asm("{ .reg .u64 t; cvta.to.shared.u64 t, %1; cvt.u32.u64 %0, t; }"
        : "=r"(r) : "l"(p));
    return r;
}
static __device__ __forceinline__ void fma2(uint64_t& acc, uint64_t a, uint64_t b) {
    asm("fma.rn.f32x2 %0, %1, %2, %0;" : "+l"(acc) : "l"(a), "l"(b));
}
static __device__ __forceinline__ uint64_t dup2(float v) {
    uint64_t r;
    asm("mov.b64 %0, {%1, %1};" : "=l"(r) : "f"(v));
    return r;
}
static __device__ __forceinline__ void lds_v2u64(uint64_t& a, uint64_t& b, uint32_t addr) {
    asm volatile("ld.shared.v2.u64 {%0, %1}, [%2];" : "=l"(a), "=l"(b) : "r"(addr));
}
static __device__ __forceinline__ void mma_tf32(float* d,
        uint32_t a0, uint32_t a1, uint32_t a2, uint32_t a3,
        uint32_t b0, uint32_t b1) {
    asm volatile(
        "mma.sync.aligned.m16n8k8.row.col.f32.tf32.tf32.f32 "
        "{%0,%1,%2,%3},{%4,%5,%6,%7},{%8,%9},{%0,%1,%2,%3};"
        : "+f"(d[0]), "+f"(d[1]), "+f"(d[2]), "+f"(d[3])
        : "r"(a0), "r"(a1), "r"(a2), "r"(a3), "r"(b0), "r"(b1));
}
static __device__ __forceinline__ void split1(float v, uint32_t& hi, uint32_t& lo) {
    uint32_t uv = __float_as_uint(v);
    hi = uv & 0xFFFFE000u;
    lo = __float_as_uint(v - __uint_as_float(hi));
}

// pre-kernel: full-K W transpose image (no swizzle; broadcast-friendly access)
__global__ void wt_kernel(const float* __restrict__ W)
{
    int g = blockIdx.x * blockDim.x + threadIdx.x;   // 0..32767
    int k = g >> 4;
    int q = g & 15;
    float4 v;
    v.x = W[(size_t)(4 * q + 0) * D_DIM + k];
    v.y = W[(size_t)(4 * q + 1) * D_DIM + k];
    v.z = W[(size_t)(4 * q + 2) * D_DIM + k];
    v.w = W[(size_t)(4 * q + 3) * D_DIM + k];
    *reinterpret_cast<float4*>(&g_wt[(size_t)g * 4]) = v;
}

// fma2 inner block for NJ tokens (tok0, tok0+32, [tok0+64])
template<int NJ>
static __device__ __forceinline__ void fma2_block(
    const float* __restrict__ xs, uint32_t wtb,
    uint64_t (&acc2)[3][4], int tok0, int col)
{
#pragma unroll
    for (int kk = 0; kk < 32; kk += 4) {
        float4 xv[NJ];
#pragma unroll
        for (int j = 0; j < NJ; j++)
            xv[j] = *reinterpret_cast<const float4*>(
                &xs[(tok0 + 32 * j) * 36 + kk]);
#pragma unroll
        for (int dk = 0; dk < 4; dk++) {
            uint64_t b0, b1, b2, b3;
            const uint32_t kb = wtb + (uint32_t)(kk + dk) * 256 + col * 32;
            lds_v2u64(b0, b1, kb);
            lds_v2u64(b2, b3, kb + 16);
#pragma unroll
            for (int j = 0; j < NJ; j++) {
                float xf = (dk == 0) ? xv[j].x : (dk == 1) ? xv[j].y
                         : (dk == 2) ? xv[j].z : xv[j].w;
                uint64_t xx = dup2(xf);
                fma2(acc2[j][0], xx, b0);
                fma2(acc2[j][1], xx, b1);
                fma2(acc2[j][2], xx, b2);
                fma2(acc2[j][3], xx, b3);
            }
        }
    }
}

__global__ __launch_bounds__(NTHREADS, 1)
void router_fused(const float* __restrict__ x, const float* __restrict__ W,
                  float* __restrict__ out)
{
    extern __shared__ __align__(16) char dsm[];
    __shared__ int tops[TM][2];

    const int tid  = threadIdx.x;
    const int wid  = tid >> 5;
    const int lane = tid & 31;
    const int qr   = lane >> 2, qc = lane & 3;       // tensor frag coords
    const int rowin = lane >> 3, col = lane & 7;     // fma2 coords
    const int cta  = blockIdx.x;
    const size_t tbase = (size_t)cta * TM;
    const uint32_t sb0 = smem_u32(dsm);

    // ---- unified chunk loader ----
    auto load_chunk = [&](int c, int s) {
        const int k0 = c * 32;
        const uint32_t bs = sb0 + (uint32_t)s * STAGE_BYTES;
#pragma unroll
        for (int p = 0; p < 4; p++) {                // xs: 1024 segs
            int seg = tid + p * NTHREADS;
            int t = seg >> 3, sk = seg & 7;
            const float* g = x + (tbase + t) * (size_t)D_DIM + k0 + sk * 4;
            CP16(bs + (uint32_t)(t * 36 + sk * 4) * 4, g);
        }
#pragma unroll
        for (int p = 0; p < 2; p++) {                // ws: 512 segs (W rows)
            int seg = tid + p * NTHREADS;
            int row = seg >> 3, sk = seg & 7;
            const float* g = W + (size_t)row * D_DIM + k0 + sk * 4;
            CP16(bs + WS_OFF + (uint32_t)(row * 36 + sk * 4) * 4, g);
        }
#pragma unroll
        for (int p = 0; p < 2; p++) {                // wt: 512 granules
            int seg = tid + p * NTHREADS;
            const float* g = g_wt + (size_t)(c * 512 + seg) * 4;
            CP16(bs + WT_OFF + (uint32_t)seg * 16, g);
        }
    };

    // tensor accumulators: 3 m16 blocks (tokens 0..47), n-group = wid
    float  acc[3][4];
    double dsum[3][4];
#pragma unroll
    for (int b = 0; b < 3; b++)
#pragma unroll
        for (int j = 0; j < 4; j++) { acc[b][j] = 0.0f; dsum[b][j] = 0.0; }

    // fma2 accumulators: tokens 48 + wid*4 + rowin + 32j (j<3 for wid<4)
    uint64_t acc2[3][4];
#pragma unroll
    for (int j = 0; j < 3; j++)
#pragma unroll
        for (int p = 0; p < 4; p++) acc2[j][p] = 0ull;
    const int tok0 = 48 + wid * 4 + rowin;

    load_chunk(0, 0); CP_COMMIT();
    load_chunk(1, 1); CP_COMMIT();

#pragma unroll 1
    for (int c = 0; c < NCH; c++) {
        CP_WAIT1();
        __syncthreads();

        const int s = c & 1;
        const float* xs = reinterpret_cast<const float*>(dsm + s * STAGE_BYTES);
        const float* ws = xs + XS_BYTES / 4;
        const uint32_t wtb = sb0 + (uint32_t)s * STAGE_BYTES + WT_OFF;

        // ---- tensor section: 4 x k8 passes, 9 HMMA each ----
#pragma unroll
        for (int k8 = 0; k8 < 4; k8++) {
            const int kc = k8 * 8 + qc;
            uint32_t bh0, bl0, bh1, bl1;
            split1(ws[(wid * 8 + qr) * 36 + kc],     bh0, bl0);
            split1(ws[(wid * 8 + qr) * 36 + kc + 4], bh1, bl1);
#pragma unroll
            for (int b = 0; b < 3; b++) {
                const int ar = (b * 16 + qr) * 36;
                uint32_t a0h, a0l, a1h, a1l, a2h, a2l, a3h, a3l;
                split1(xs[ar + kc],           a0h, a0l);
                split1(xs[ar + 288 + kc],     a1h, a1l);   // +8 rows * 36
                split1(xs[ar + kc + 4],       a2h, a2l);
                split1(xs[ar + 288 + kc + 4], a3h, a3l);
                mma_tf32(acc[b], a0h, a1h, a2h, a3h, bh0, bh1);
                mma_tf32(acc[b], a0h, a1h, a2h, a3h, bl0, bl1);
                mma_tf32(acc[b], a0l, a1l, a2l, a3l, bh0, bh1);
            }
        }

        // ---- fma2 section (tokens 48..127) ----
        if (wid < 4) fma2_block<3>(xs, wtb, acc2, tok0, col);
        else         fma2_block<2>(xs, wtb, acc2, tok0, col);

        // drain tensor accs to fp64 every 16 chunks (caps fp32 chain at 192)
        if ((c & 15) == 15) {
#pragma unroll
            for (int b = 0; b < 3; b++)
#pragma unroll
                for (int j = 0; j < 4; j++) {
                    dsum[b][j] += (double)acc[b][j];
                    acc[b][j] = 0.0f;
                }
        }

        __syncthreads();               // all reads of stage s done
        if (c + 2 < NCH) load_chunk(c + 2, s);
        CP_COMMIT();
    }
    __syncthreads();

    // ---- epilogue: logits into probs overlay [128][66] ----
    float* probs = reinterpret_cast<float*>(dsm);

    // tensor tokens 0..47
#pragma unroll
    for (int b = 0; b < 3; b++) {
        const int tr0 = b * 16 + qr;
        const int cb  = wid * 8 + qc * 2;
        *reinterpret_cast<float2*>(&probs[tr0 * 66 + cb]) =
            make_float2((float)dsum[b][0], (float)dsum[b][1]);
        *reinterpret_cast<float2*>(&probs[(tr0 + 8) * 66 + cb]) =
            make_float2((float)dsum[b][2], (float)dsum[b][3]);
    }
    // fma2 tokens 48..127
    const int nj = (wid < 4) ? 3 : 2;
    for (int j = 0; j < nj; j++) {
        const int t = tok0 + 32 * j;
#pragma unroll
        for (int p = 0; p < 4; p++) {
            float lo = __uint_as_float((uint32_t)acc2[j][p]);
            float hi = __uint_as_float((uint32_t)(acc2[j][p] >> 32));
            *reinterpret_cast<float2*>(&probs[t * 66 + col * 8 + p * 2]) =
                make_float2(lo, hi);
        }
    }
    __syncthreads();

    // one thread per token: softmax + top-2 + gates + outputs
    if (tid < TM) {
        const int t = tid;
        float f[64];
#pragma unroll
        for (int e = 0; e < E_EXP; e++) f[e] = probs[t * 66 + e];
        float mx = f[0];
#pragma unroll
        for (int e = 1; e < E_EXP; e++) mx = fmaxf(mx, f[e]);
        float S = 0.0f, b1 = -1.0f, b2 = -1.0f;
        int i1 = 0, i2 = 0;
#pragma unroll
        for (int e = 0; e < E_EXP; e++) {
            float v = expf(f[e] - mx);
            f[e] = v;
            S += v;
            if (v > b1) { b2 = b1; i2 = i1; b1 = v; i1 = e; }
            else if (v > b2) { b2 = v; i2 = e; }
        }
        const float invS = 1.0f / S;
#pragma unroll
        for (int e = 0; e < E_EXP; e++) probs[t * 66 + e] = f[e] * invS;
        tops[t][0] = i1;
        tops[t][1] = i2;

        const float p1 = b1 * invS, p2 = b2 * invS;
        const float denom = p1 + p2 + 1e-9f;
        const size_t gt = tbase + t;
        out[gt * 2 + 0] = (float)i1;
        out[gt * 2 + 1] = (float)i2;
        out[(size_t)M_TOKENS * 2 + gt * 2 + 0] = p1 / denom;
        out[(size_t)M_TOKENS * 2 + gt * 2 + 1] = p2 / denom;
    }
    __syncthreads();

    // deterministic per-CTA partials (counts, prob sums)
    if (tid < E_EXP) {
        const int e = tid;
        float cnt = 0.0f, sp = 0.0f;
#pragma unroll 4
        for (int t = 0; t < TM; t++) {
            sp  += probs[t * 66 + e];
            cnt += (float)((tops[t][0] == e) + (tops[t][1] == e));
        }
        g_partials[cta * 128 + e]      = cnt;
        g_partials[cta * 128 + 64 + e] = sp;
    }
}

__global__ void aux_kernel2(float* __restrict__ out)
{
    __shared__ float sC[16][64];
    __shared__ float sP[16][64];
    __shared__ float red[64];
    const int t = threadIdx.x;          // 1024 threads
    const int c = t >> 6, e = t & 63;
    float C = 0.0f, P = 0.0f;
#pragma unroll
    for (int j = 0; j < 8; j++) {
        const int b = c + 16 * j;
        C += g_partials[b * 128 + e];
        P += g_partials[b * 128 + 64 + e];
    }
    sC[c][e] = C; sP[c][e] = P;
    __syncthreads();
    if (t < 64) {
        float Ct = 0.0f, Pt = 0.0f;
#pragma unroll
        for (int j = 0; j < 16; j++) { Ct += sC[j][t]; Pt += sP[j][t]; }
        red[t] = Ct * Pt;
    }
    __syncthreads();
#pragma unroll
    for (int s = 32; s > 0; s >>= 1) {
        if (t < s) red[t] += red[t + s];
        __syncthreads();
    }
    if (t == 0)
        out[(size_t)M_TOKENS * 4] =
            0.01f * 64.0f * red[0] / (32768.0f * 16384.0f);
}

extern "C" void kernel_launch(void* const* d_in, const int* in_sizes, int n_in,
                              void* d_out, int out_size)
{
    const float* x = (const float*)d_in[0];   // [4,4096,2048] f32
    const float* W = (const float*)d_in[1];   // [64,2048] f32
    float* out = (float*)d_out;               // [32768 idx | 32768 gates | 1 aux]

    cudaFuncSetAttribute(router_fused,
                         cudaFuncAttributeMaxDynamicSharedMemorySize, DYN_BYTES);

    wt_kernel<<<128, 256>>>(W);
    router_fused<<<NCTA, NTHREADS, DYN_BYTES>>>(x, W, out);
    aux_kernel2<<<1, 1024>>>(out);
}

// round 9
// speedup vs baseline: 1.1074x; 1.1074x over previous
#include <cuda_runtime.h>
#include <math.h>
#include <stdint.h>

// Problem: B=4, S=4096, D=2048, E=64, K=2
#define M_TOKENS 16384
#define D_DIM    2048
#define E_EXP    64
#define TM       128
#define NCTA     (M_TOKENS / TM)       // 128
#define NTHREADS 256
#define NCH      64                    // k32 chunks

// Stage layout (bytes): xs [128 tok x 36f], ws [64 exp x 36f], wt [32k x 16 gran x 16B]
#define XS_BYTES (128 * 36 * 4)        // 18432
#define WS_OFF   XS_BYTES
#define WS_BYTES (64 * 36 * 4)         // 9216
#define WT_OFF   (WS_OFF + WS_BYTES)   // 27648
#define WT_BYTES (32 * 16 * 16)        // 8192
#define STAGE_BYTES (WT_OFF + WT_BYTES)    // 35840
#define DYN_BYTES   (2 * STAGE_BYTES)      // 71680

__device__ float g_partials[NCTA * 128];
// Full-K W transpose image: granule (k,q) = experts 4q..4q+3 at column k
__device__ __align__(16) float g_wt[D_DIM * E_EXP];

#define CP16(smem_a, gptr) \
    asm volatile("cp.async.cg.shared.global [%0], [%1], 16;" \
                 :: "r"(smem_a), "l"(gptr) : "memory")
#define CP_COMMIT() asm volatile("cp.async.commit_group;" ::: "memory")
#define CP_WAIT1()  asm volatile("cp.async.wait_group 1;" ::: "memory")

static __device__ __forceinline__ uint32_t smem_u32(const void* p) {
    uint32_t r;
    asm("{ .reg .u64 t; cvta.to.shared.u64 t, %1; cvt.u32.u64 %0, t; }"
        : "=r"(r) : "l"(p));
    return r;
}
static __device__ __forceinline__ void fma2(uint64_t& acc, uint64_t a, uint64_t b) {
    asm("fma.rn.f32x2 %0, %1, %2, %0;" : "+l"(acc) : "l"(a), "l"(b));
}
static __device__ __forceinline__ uint64_t dup2(float v) {
    uint64_t r;
    asm("mov.b64 %0, {%1, %1};" : "=l"(r) : "f"(v));
    return r;
}
static __device__ __forceinline__ void lds_v2u64(uint64_t& a, uint64_t& b, uint32_t addr) {
    asm volatile("ld.shared.v2.u64 {%0, %1}, [%2];" : "=l"(a), "=l"(b) : "r"(addr));
}
static __device__ __forceinline__ void mma_tf32(float* d,
        uint32_t a0, uint32_t a1, uint32_t a2, uint32_t a3,
        uint32_t b0, uint32_t b1) {
    asm volatile(
        "mma.sync.aligned.m16n8k8.row.col.f32.tf32.tf32.f32 "
        "{%0,%1,%2,%3},{%4,%5,%6,%7},{%8,%9},{%0,%1,%2,%3};"
        : "+f"(d[0]), "+f"(d[1]), "+f"(d[2]), "+f"(d[3])
        : "r"(a0), "r"(a1), "r"(a2), "r"(a3), "r"(b0), "r"(b1));
}
static __device__ __forceinline__ void split1(float v, uint32_t& hi, uint32_t& lo) {
    uint32_t uv = __float_as_uint(v);
    hi = uv & 0xFFFFE000u;
    lo = __float_as_uint(v - __uint_as_float(hi));
}

// pre-kernel: full-K W transpose image
__global__ void wt_kernel(const float* __restrict__ W)
{
    int g = blockIdx.x * blockDim.x + threadIdx.x;   // 0..32767
    int k = g >> 4;
    int q = g & 15;
    float4 v;
    v.x = W[(size_t)(4 * q + 0) * D_DIM + k];
    v.y = W[(size_t)(4 * q + 1) * D_DIM + k];
    v.z = W[(size_t)(4 * q + 2) * D_DIM + k];
    v.w = W[(size_t)(4 * q + 3) * D_DIM + k];
    *reinterpret_cast<float4*>(&g_wt[(size_t)g * 4]) = v;
}

__global__ __launch_bounds__(NTHREADS, 1)
void router_fused(const float* __restrict__ x, const float* __restrict__ W,
                  float* __restrict__ out)
{
    extern __shared__ __align__(16) char dsm[];
    __shared__ int tops[TM][2];

    const int tid  = threadIdx.x;
    const int wid  = tid >> 5;
    const int lane = tid & 31;
    const int qr   = lane >> 2, qc = lane & 3;       // tensor frag coords
    const int rowin = lane >> 3, col = lane & 7;     // fma2 coords
    const int cta  = blockIdx.x;
    const size_t tbase = (size_t)cta * TM;
    const uint32_t sb0 = smem_u32(dsm);

    // ---- unified chunk loader (identical to R8, proven) ----
    auto load_chunk = [&](int c, int s) {
        const int k0 = c * 32;
        const uint32_t bs = sb0 + (uint32_t)s * STAGE_BYTES;
#pragma unroll
        for (int p = 0; p < 4; p++) {                // xs: 1024 segs
            int seg = tid + p * NTHREADS;
            int t = seg >> 3, sk = seg & 7;
            const float* g = x + (tbase + t) * (size_t)D_DIM + k0 + sk * 4;
            CP16(bs + (uint32_t)(t * 36 + sk * 4) * 4, g);
        }
#pragma unroll
        for (int p = 0; p < 2; p++) {                // ws: 512 segs (W rows)
            int seg = tid + p * NTHREADS;
            int row = seg >> 3, sk = seg & 7;
            const float* g = W + (size_t)row * D_DIM + k0 + sk * 4;
            CP16(bs + WS_OFF + (uint32_t)(row * 36 + sk * 4) * 4, g);
        }
#pragma unroll
        for (int p = 0; p < 2; p++) {                // wt: 512 granules
            int seg = tid + p * NTHREADS;
            const float* g = g_wt + (size_t)(c * 512 + seg) * 4;
            CP16(bs + WT_OFF + (uint32_t)seg * 16, g);
        }
    };

    // tensor: tokens 0..63 (4 m16 blocks), n-group = wid
    float acc[4][4], sum32[4][4];
#pragma unroll
    for (int b = 0; b < 4; b++)
#pragma unroll
        for (int j = 0; j < 4; j++) { acc[b][j] = 0.0f; sum32[b][j] = 0.0f; }

    // fma2: tokens 64..127 -> tok0, tok0+32; experts col*8..col*8+7 (4 pairs)
    uint64_t acc2[2][4];
#pragma unroll
    for (int j = 0; j < 2; j++)
#pragma unroll
        for (int p = 0; p < 4; p++) acc2[j][p] = 0ull;
    const int tok0 = 64 + wid * 4 + rowin;

    load_chunk(0, 0); CP_COMMIT();
    load_chunk(1, 1); CP_COMMIT();

#pragma unroll 1
    for (int c = 0; c < NCH; c++) {
        CP_WAIT1();
        __syncthreads();

        const int s = c & 1;
        const float* xs = reinterpret_cast<const float*>(dsm + s * STAGE_BYTES);
        const float* ws = xs + XS_BYTES / 4;
        const uint32_t wtb = sb0 + (uint32_t)s * STAGE_BYTES + WT_OFF;

        auto tensor_sec = [&]() {
#pragma unroll
            for (int k8 = 0; k8 < 4; k8++) {
                const int kc = k8 * 8 + qc;
                uint32_t bh0, bl0, bh1, bl1;
                split1(ws[(wid * 8 + qr) * 36 + kc],     bh0, bl0);
                split1(ws[(wid * 8 + qr) * 36 + kc + 4], bh1, bl1);
#pragma unroll
                for (int b = 0; b < 4; b++) {
                    const int ar = (b * 16 + qr) * 36;
                    uint32_t a0h, a0l, a1h, a1l, a2h, a2l, a3h, a3l;
                    split1(xs[ar + kc],           a0h, a0l);
                    split1(xs[ar + 288 + kc],     a1h, a1l);
                    split1(xs[ar + kc + 4],       a2h, a2l);
                    split1(xs[ar + 288 + kc + 4], a3h, a3l);
                    mma_tf32(acc[b], a0h, a1h, a2h, a3h, bh0, bh1);
                    mma_tf32(acc[b], a0h, a1h, a2h, a3h, bl0, bl1);
                    mma_tf32(acc[b], a0l, a1l, a2l, a3l, bh0, bh1);
                }
            }
        };

        auto fma2_sec = [&]() {
#pragma unroll
            for (int kk = 0; kk < 32; kk += 4) {
                float4 xv0 = *reinterpret_cast<const float4*>(&xs[tok0 * 36 + kk]);
                float4 xv1 = *reinterpret_cast<const float4*>(&xs[(tok0 + 32) * 36 + kk]);
#pragma unroll
                for (int dk = 0; dk < 4; dk++) {
                    uint64_t b0, b1, b2, b3;
                    const uint32_t kb = wtb + (uint32_t)(kk + dk) * 256 + col * 32;
                    lds_v2u64(b0, b1, kb);
                    lds_v2u64(b2, b3, kb + 16);
                    float x0 = (dk == 0) ? xv0.x : (dk == 1) ? xv0.y
                             : (dk == 2) ? xv0.z : xv0.w;
                    float x1 = (dk == 0) ? xv1.x : (dk == 1) ? xv1.y
                             : (dk == 2) ? xv1.z : xv1.w;
                    uint64_t xx0 = dup2(x0), xx1 = dup2(x1);
                    fma2(acc2[0][0], xx0, b0);
                    fma2(acc2[0][1], xx0, b1);
                    fma2(acc2[0][2], xx0, b2);
                    fma2(acc2[0][3], xx0, b3);
                    fma2(acc2[1][0], xx1, b0);
                    fma2(acc2[1][1], xx1, b1);
                    fma2(acc2[1][2], xx1, b2);
                    fma2(acc2[1][3], xx1, b3);
                }
            }
        };

        // staggered phases: each SMSP (warps w, w+4) runs one of each per phase
        if (wid < 4) { tensor_sec(); fma2_sec(); }
        else         { fma2_sec(); tensor_sec(); }

        // drain tensor accs into fp32 sums every 16 chunks
        // (within-acc chain <=192 adds on ~0.3-magnitude partials; drain chain 4)
        if ((c & 15) == 15) {
#pragma unroll
            for (int b = 0; b < 4; b++)
#pragma unroll
                for (int j = 0; j < 4; j++) {
                    sum32[b][j] += acc[b][j];
                    acc[b][j] = 0.0f;
                }
        }

        __syncthreads();               // all reads of stage s done
        if (c + 2 < NCH) load_chunk(c + 2, s);
        CP_COMMIT();
    }
    __syncthreads();

    // ---- epilogue: logits into probs overlay [128][66] ----
    float* probs = reinterpret_cast<float*>(dsm);

    // tensor tokens 0..63
#pragma unroll
    for (int b = 0; b < 4; b++) {
        const int tr0 = b * 16 + qr;
        const int cb  = wid * 8 + qc * 2;
        *reinterpret_cast<float2*>(&probs[tr0 * 66 + cb]) =
            make_float2(sum32[b][0], sum32[b][1]);
        *reinterpret_cast<float2*>(&probs[(tr0 + 8) * 66 + cb]) =
            make_float2(sum32[b][2], sum32[b][3]);
    }
    // fma2 tokens 64..127
#pragma unroll
    for (int j = 0; j < 2; j++) {
        const int t = tok0 + 32 * j;
#pragma unroll
        for (int p = 0; p < 4; p++) {
            float lo = __uint_as_float((uint32_t)acc2[j][p]);
            float hi = __uint_as_float((uint32_t)(acc2[j][p] >> 32));
            *reinterpret_cast<float2*>(&probs[t * 66 + col * 8 + p * 2]) =
                make_float2(lo, hi);
        }
    }
    __syncthreads();

    // one thread per token: softmax + top-2 + gates + outputs
    if (tid < TM) {
        const int t = tid;
        float f[64];
#pragma unroll
        for (int e = 0; e < E_EXP; e++) f[e] = probs[t * 66 + e];
        float mx = f[0];
#pragma unroll
        for (int e = 1; e < E_EXP; e++) mx = fmaxf(mx, f[e]);
        float S = 0.0f, b1 = -1.0f, b2 = -1.0f;
        int i1 = 0, i2 = 0;
#pragma unroll
        for (int e = 0; e < E_EXP; e++) {
            float v = expf(f[e] - mx);
            f[e] = v;
            S += v;
            if (v > b1) { b2 = b1; i2 = i1; b1 = v; i1 = e; }
            else if (v > b2) { b2 = v; i2 = e; }
        }
        const float invS = 1.0f / S;
#pragma unroll
        for (int e = 0; e < E_EXP; e++) probs[t * 66 + e] = f[e] * invS;
        tops[t][0] = i1;
        tops[t][1] = i2;

        const float p1 = b1 * invS, p2 = b2 * invS;
        const float denom = p1 + p2 + 1e-9f;
        const size_t gt = tbase + t;
        out[gt * 2 + 0] = (float)i1;
        out[gt * 2 + 1] = (float)i2;
        out[(size_t)M_TOKENS * 2 + gt * 2 + 0] = p1 / denom;
        out[(size_t)M_TOKENS * 2 + gt * 2 + 1] = p2 / denom;
    }
    __syncthreads();

    // deterministic per-CTA partials (counts, prob sums)
    if (tid < E_EXP) {
        const int e = tid;
        float cnt = 0.0f, sp = 0.0f;
#pragma unroll 4
        for (int t = 0; t < TM; t++) {
            sp  += probs[t * 66 + e];
            cnt += (float)((tops[t][0] == e) + (tops[t][1] == e));
        }
        g_partials[cta * 128 + e]      = cnt;
        g_partials[cta * 128 + 64 + e] = sp;
    }
}

__global__ void aux_kernel2(float* __restrict__ out)
{
    __shared__ float sC[16][64];
    __shared__ float sP[16][64];
    __shared__ float red[64];
    const int t = threadIdx.x;          // 1024 threads
    const int c = t >> 6, e = t & 63;
    float C = 0.0f, P = 0.0f;
#pragma unroll
    for (int j = 0; j < 8; j++) {
        const int b = c + 16 * j;
        C += g_partials[b * 128 + e];
        P += g_partials[b * 128 + 64 + e];
    }
    sC[c][e] = C; sP[c][e] = P;
    __syncthreads();
    if (t < 64) {
        float Ct = 0.0f, Pt = 0.0f;
#pragma unroll
        for (int j = 0; j < 16; j++) { Ct += sC[j][t]; Pt += sP[j][t]; }
        red[t] = Ct * Pt;
    }
    __syncthreads();
#pragma unroll
    for (int s = 32; s > 0; s >>= 1) {
        if (t < s) red[t] += red[t + s];
        __syncthreads();
    }
    if (t == 0)
        out[(size_t)M_TOKENS * 4] =
            0.01f * 64.0f * red[0] / (32768.0f * 16384.0f);
}

extern "C" void kernel_launch(void* const* d_in, const int* in_sizes, int n_in,
                              void* d_out, int out_size)
{
    const float* x = (const float*)d_in[0];   // [4,4096,2048] f32
    const float* W = (const float*)d_in[1];   // [64,2048] f32
    float* out = (float*)d_out;               // [32768 idx | 32768 gates | 1 aux]

    cudaFuncSetAttribute(router_fused,
                         cudaFuncAttributeMaxDynamicSharedMemorySize, DYN_BYTES);

    wt_kernel<<<128, 256>>>(W);
    router_fused<<<NCTA, NTHREADS, DYN_BYTES>>>(x, W, out);
    aux_kernel2<<<1, 1024>>>(out);
}

// round 10
// speedup vs baseline: 2.0410x; 1.8432x over previous
#include <cuda_runtime.h>
#include <cuda_fp16.h>
#include <math.h>
#include <stdint.h>

// Problem: B=4, S=4096, D=2048, E=64, K=2
#define M_TOKENS 16384
#define D_DIM    2048
#define E_EXP    64
#define TM       128
#define NCTA     (M_TOKENS / TM)       // 128
#define NTHREADS 256
#define NCH      64                    // k32 chunks
#define WSCALE   1024.0f               // exact pow2 pre-scale of W (fp16 subnormal fix)

// Stage: xs [128 tok x 36 f32] + wh [2 kstep x 8 pair x 64 e, f16x2] + wl same
#define XS_BYTES (128 * 36 * 4)        // 18432
#define WH_OFF   XS_BYTES
#define WH_BYTES 4096                  // 2*8*64 u32
#define WL_OFF   (WH_OFF + WH_BYTES)
#define STAGE_BYTES (WL_OFF + WH_BYTES)    // 26624
#define DYN_BYTES   (2 * STAGE_BYTES)      // 53248

__device__ float g_partials[NCTA * 128];
// W split images, scaled by WSCALE: u32 f16x2 of k-pair, layout [kstep][pair][e]
__device__ __align__(16) uint32_t g_wh[D_DIM / 2 * E_EXP / 8 * 8];  // 65536 u32
__device__ __align__(16) uint32_t g_wl[D_DIM / 2 * E_EXP / 8 * 8];

#define CP16(smem_a, gptr) \
    asm volatile("cp.async.cg.shared.global [%0], [%1], 16;" \
                 :: "r"(smem_a), "l"(gptr) : "memory")
#define CP_COMMIT() asm volatile("cp.async.commit_group;" ::: "memory")
#define CP_WAIT1()  asm volatile("cp.async.wait_group 1;" ::: "memory")

static __device__ __forceinline__ uint32_t smem_u32(const void* p) {
    uint32_t r;
    asm("{ .reg .u64 t; cvta.to.shared.u64 t, %1; cvt.u32.u64 %0, t; }"
        : "=r"(r) : "l"(p));
    return r;
}

static __device__ __forceinline__ void mma_f16(float* d,
        uint32_t a0, uint32_t a1, uint32_t a2, uint32_t a3,
        uint32_t b0, uint32_t b1) {
    asm volatile(
        "mma.sync.aligned.m16n8k16.row.col.f32.f16.f16.f32 "
        "{%0,%1,%2,%3},{%4,%5,%6,%7},{%8,%9},{%0,%1,%2,%3};"
        : "+f"(d[0]), "+f"(d[1]), "+f"(d[2]), "+f"(d[3])
        : "r"(a0), "r"(a1), "r"(a2), "r"(a3), "r"(b0), "r"(b1));
}

// split float2 (k-pair) into hi f16x2 and lo f16x2 (lo = v - hi, exact in f32)
static __device__ __forceinline__ void split_pair(float2 v, uint32_t& h, uint32_t& l) {
    __half2 hh = __floats2half2_rn(v.x, v.y);           // lo half = v.x
    float2 hb = __half22float2(hh);
    __half2 ll = __floats2half2_rn(v.x - hb.x, v.y - hb.y);
    h = *reinterpret_cast<uint32_t*>(&hh);
    l = *reinterpret_cast<uint32_t*>(&ll);
}

// pre-kernel: build scaled hi/lo W images. layout [kstep][pair][e].
__global__ void wsplit_kernel(const float* __restrict__ W)
{
    int g = blockIdx.x * blockDim.x + threadIdx.x;   // 0..65535
    int e  = g & 63;
    int kp = g >> 6;                                 // k-pair 0..1023
    float2 v;
    v.x = W[(size_t)e * D_DIM + 2 * kp]     * WSCALE;
    v.y = W[(size_t)e * D_DIM + 2 * kp + 1] * WSCALE;
    uint32_t h, l;
    split_pair(v, h, l);
    int idx = (((kp >> 3) * 8 + (kp & 7)) * 64) + e;
    g_wh[idx] = h;
    g_wl[idx] = l;
}

__global__ __launch_bounds__(NTHREADS, 1)
void router_f16(const float* __restrict__ x, float* __restrict__ out)
{
    extern __shared__ __align__(16) char dsm[];
    __shared__ int tops[TM][2];

    const int tid  = threadIdx.x;
    const int wid  = tid >> 5;     // warp owns m-block wid (tokens 16w..16w+15)
    const int lane = tid & 31;
    const int qr   = lane >> 2, qc = lane & 3;
    const int cta  = blockIdx.x;
    const size_t tbase = (size_t)cta * TM;
    const uint32_t sb0 = smem_u32(dsm);

    // ---- async loader: chunk c -> stage s ----
    auto load_chunk = [&](int c, int s) {
        const int k0 = c * 32;
        const uint32_t bs = sb0 + (uint32_t)s * STAGE_BYTES;
#pragma unroll
        for (int p = 0; p < 4; p++) {                 // xs: 1024 segs of 16B
            int seg = tid + p * NTHREADS;
            int t = seg >> 3, sk = seg & 7;
            const float* g = x + (tbase + t) * (size_t)D_DIM + k0 + sk * 4;
            CP16(bs + (uint32_t)(t * 36 + sk * 4) * 4, g);
        }
        {                                             // wh: 256 segs (4096 B)
            const uint32_t* g = g_wh + (size_t)c * 1024 + tid * 4;
            CP16(bs + WH_OFF + (uint32_t)tid * 16, g);
        }
        {                                             // wl: 256 segs
            const uint32_t* g = g_wl + (size_t)c * 1024 + tid * 4;
            CP16(bs + WL_OFF + (uint32_t)tid * 16, g);
        }
    };

    float acc[8][4], sum32[8][4];
#pragma unroll
    for (int n = 0; n < 8; n++)
#pragma unroll
        for (int j = 0; j < 4; j++) { acc[n][j] = 0.0f; sum32[n][j] = 0.0f; }

    load_chunk(0, 0); CP_COMMIT();
    load_chunk(1, 1); CP_COMMIT();

    // A-frag source rows (fixed per thread)
    const int ar0 = (wid * 16 + qr) * 36;       // row qr
    const int ar1 = ar0 + 8 * 36;               // row qr+8

#pragma unroll 1
    for (int c = 0; c < NCH; c++) {
        CP_WAIT1();
        __syncthreads();

        const int s = c & 1;
        const float* xs = reinterpret_cast<const float*>(dsm + s * STAGE_BYTES);
        const uint32_t whb = sb0 + (uint32_t)s * STAGE_BYTES + WH_OFF;
        const uint32_t wlb = whb + WH_BYTES;

#pragma unroll
        for (int ks = 0; ks < 2; ks++) {            // k16 steps
            // A fragments: rows (qr, qr+8), k-pairs (2qc, 2qc+8) within this k16
            const int kb = ks * 16 + 2 * qc;
            uint32_t a0h, a0l, a1h, a1l, a2h, a2l, a3h, a3l;
            split_pair(*reinterpret_cast<const float2*>(&xs[ar0 + kb]),     a0h, a0l);
            split_pair(*reinterpret_cast<const float2*>(&xs[ar1 + kb]),     a1h, a1l);
            split_pair(*reinterpret_cast<const float2*>(&xs[ar0 + kb + 8]), a2h, a2l);
            split_pair(*reinterpret_cast<const float2*>(&xs[ar1 + kb + 8]), a3h, a3l);

#pragma unroll
            for (int n = 0; n < 8; n++) {
                // B frags: e = n*8+qr; pairs qc and qc+4 in this kstep
                const uint32_t off0 = (uint32_t)(((ks * 8 + qc) * 64) + n * 8 + qr) * 4;
                const uint32_t off1 = (uint32_t)(((ks * 8 + qc + 4) * 64) + n * 8 + qr) * 4;
                uint32_t bh0, bh1, bl0, bl1;
                asm volatile("ld.shared.b32 %0, [%1];" : "=r"(bh0) : "r"(whb + off0));
                asm volatile("ld.shared.b32 %0, [%1];" : "=r"(bh1) : "r"(whb + off1));
                asm volatile("ld.shared.b32 %0, [%1];" : "=r"(bl0) : "r"(wlb + off0));
                asm volatile("ld.shared.b32 %0, [%1];" : "=r"(bl1) : "r"(wlb + off1));
                mma_f16(acc[n], a0h, a1h, a2h, a3h, bh0, bh1);
                mma_f16(acc[n], a0h, a1h, a2h, a3h, bl0, bl1);
                mma_f16(acc[n], a0l, a1l, a2l, a3l, bh0, bh1);
            }
        }

        // drain to fp32 sums every 16 chunks (caps chain at 96 accumulates)
        if ((c & 15) == 15) {
#pragma unroll
            for (int n = 0; n < 8; n++)
#pragma unroll
                for (int j = 0; j < 4; j++) {
                    sum32[n][j] += acc[n][j];
                    acc[n][j] = 0.0f;
                }
        }

        __syncthreads();
        if (c + 2 < NCH) load_chunk(c + 2, s);
        CP_COMMIT();
    }
    __syncthreads();

    // ---- epilogue: logits (unscaled by 1/WSCALE) into overlay [128][66] ----
    float* probs = reinterpret_cast<float*>(dsm);
    const float inv_ws = 1.0f / WSCALE;
    {
        const int tr0 = wid * 16 + qr;
#pragma unroll
        for (int n = 0; n < 8; n++) {
            const int cb = n * 8 + qc * 2;
            *reinterpret_cast<float2*>(&probs[tr0 * 66 + cb]) =
                make_float2(sum32[n][0] * inv_ws, sum32[n][1] * inv_ws);
            *reinterpret_cast<float2*>(&probs[(tr0 + 8) * 66 + cb]) =
                make_float2(sum32[n][2] * inv_ws, sum32[n][3] * inv_ws);
        }
    }
    __syncthreads();

    // one thread per token: softmax + top-2 + gates + outputs
    if (tid < TM) {
        const int t = tid;
        float f[64];
#pragma unroll
        for (int e = 0; e < E_EXP; e++) f[e] = probs[t * 66 + e];
        float mx = f[0];
#pragma unroll
        for (int e = 1; e < E_EXP; e++) mx = fmaxf(mx, f[e]);
        float S = 0.0f, b1 = -1.0f, b2 = -1.0f;
        int i1 = 0, i2 = 0;
#pragma unroll
        for (int e = 0; e < E_EXP; e++) {
            float v = expf(f[e] - mx);
            f[e] = v;
            S += v;
            if (v > b1) { b2 = b1; i2 = i1; b1 = v; i1 = e; }
            else if (v > b2) { b2 = v; i2 = e; }
        }
        const float invS = 1.0f / S;
#pragma unroll
        for (int e = 0; e < E_EXP; e++) probs[t * 66 + e] = f[e] * invS;
        tops[t][0] = i1;
        tops[t][1] = i2;

        const float p1 = b1 * invS, p2 = b2 * invS;
        const float denom = p1 + p2 + 1e-9f;
        const size_t gt = tbase + t;
        out[gt * 2 + 0] = (float)i1;
        out[gt * 2 + 1] = (float)i2;
        out[(size_t)M_TOKENS * 2 + gt * 2 + 0] = p1 / denom;
        out[(size_t)M_TOKENS * 2 + gt * 2 + 1] = p2 / denom;
    }
    __syncthreads();

    // deterministic per-CTA partials (counts, prob sums)
    if (tid < E_EXP) {
        const int e = tid;
        float cnt = 0.0f, sp = 0.0f;
#pragma unroll 4
        for (int t = 0; t < TM; t++) {
            sp  += probs[t * 66 + e];
            cnt += (float)((tops[t][0] == e) + (tops[t][1] == e));
        }
        g_partials[cta * 128 + e]      = cnt;
        g_partials[cta * 128 + 64 + e] = sp;
    }
}

__global__ void aux_kernel2(float* __restrict__ out)
{
    __shared__ float sC[16][64];
    __shared__ float sP[16][64];
    __shared__ float red[64];
    const int t = threadIdx.x;          // 1024 threads
    const int c = t >> 6, e = t & 63;
    float C = 0.0f, P = 0.0f;
#pragma unroll
    for (int j = 0; j < 8; j++) {
        const int b = c + 16 * j;
        C += g_partials[b * 128 + e];
        P += g_partials[b * 128 + 64 + e];
    }
    sC[c][e] = C; sP[c][e] = P;
    __syncthreads();
    if (t < 64) {
        float Ct = 0.0f, Pt = 0.0f;
#pragma unroll
        for (int j = 0; j < 16; j++) { Ct += sC[j][t]; Pt += sP[j][t]; }
        red[t] = Ct * Pt;
    }
    __syncthreads();
#pragma unroll
    for (int s = 32; s > 0; s >>= 1) {
        if (t < s) red[t] += red[t + s];
        __syncthreads();
    }
    if (t == 0)
        out[(size_t)M_TOKENS * 4] =
            0.01f * 64.0f * red[0] / (32768.0f * 16384.0f);
}

extern "C" void kernel_launch(void* const* d_in, const int* in_sizes, int n_in,
                              void* d_out, int out_size)
{
    const float* x = (const float*)d_in[0];   // [4,4096,2048] f32
    const float* W = (const float*)d_in[1];   // [64,2048] f32
    float* out = (float*)d_out;               // [32768 idx | 32768 gates | 1 aux]

    cudaFuncSetAttribute(router_f16,
                         cudaFuncAttributeMaxDynamicSharedMemorySize, DYN_BYTES);

    wsplit_kernel<<<256, 256>>>(W);
    router_f16<<<NCTA, NTHREADS, DYN_BYTES>>>(x, out);
    aux_kernel2<<<1, 1024>>>(out);
}